// round 2
// baseline (speedup 1.0000x reference)
#include <cuda_runtime.h>
#include <cstdint>

// ---------------- problem-size constants ----------------
#define MAXN 50000
#define MAXE 800000
#define MAXET (MAXE + MAXN)   // edges + self loops
#define NG 64                 // graphs

// ---------------- scratch (device globals; allocation-free) ----------------
__device__ float    g_xs1[(size_t)MAXN * 256];
__device__ float    g_xd1[(size_t)MAXN * 256];
__device__ float    g_h  [(size_t)MAXN * 256];
__device__ float    g_agg1[(size_t)MAXN * 256];
__device__ float    g_score1[(size_t)MAXET * 4];
__device__ unsigned g_smax1[MAXN * 4];
__device__ float    g_denom1[MAXN * 4];

__device__ float    g_xs2[(size_t)MAXN * 64];
__device__ float    g_xd2[(size_t)MAXN * 64];
__device__ float    g_agg2[(size_t)MAXN * 64];
__device__ float    g_score2[MAXET];
__device__ unsigned g_smax2[MAXN];
__device__ float    g_denom2[MAXN];

__device__ float    g_pool[NG * 64];
__device__ float    g_cnt[NG];

// orderable-uint encoding of float for atomicMax
__device__ __forceinline__ unsigned fenc(float f) {
    unsigned u = __float_as_uint(f);
    return (u & 0x80000000u) ? ~u : (u | 0x80000000u);
}
__device__ __forceinline__ float fdec(unsigned u) {
    return __uint_as_float((u & 0x80000000u) ? (u ^ 0x80000000u) : ~u);
}
#define ENC_NEG_INF 0x007FFFFFu   // fenc(-inf)

__device__ __forceinline__ float lrelu(float v) {
    return v > 0.0f ? v : 0.2f * v;
}

// ---------------- init ----------------
__global__ void init_kernel(int N) {
    size_t stride = (size_t)gridDim.x * blockDim.x;
    size_t total = (size_t)N * 256;
    for (size_t i = (size_t)blockIdx.x * blockDim.x + threadIdx.x; i < total; i += stride) {
        g_agg1[i] = 0.0f;
        if (i < (size_t)N * 64) g_agg2[i] = 0.0f;
        if (i < (size_t)N * 4) { g_denom1[i] = 0.0f; g_smax1[i] = ENC_NEG_INF; }
        if (i < (size_t)N)     { g_denom2[i] = 0.0f; g_smax2[i] = ENC_NEG_INF; }
        if (i < NG * 64)       g_pool[i] = 0.0f;
        if (i < NG)            g_cnt[i] = 0.0f;
    }
}

// ---------------- GEMM: C[M,Ncol] = A[M,K] @ W[K,Ncol] + bias ----------------
// BM=64, BN=64, BK=16, 256 threads, 4x4 per thread
__global__ void gemm_bias(const float* __restrict__ A, const float* __restrict__ W,
                          const float* __restrict__ bias, float* __restrict__ C,
                          int M, int K, int Ncol) {
    __shared__ float As[16][64];
    __shared__ float Ws[16][64];
    const int t  = threadIdx.x;
    const int tx = t & 15;
    const int ty = t >> 4;
    const int row0 = blockIdx.y * 64;
    const int col0 = blockIdx.x * 64;

    float acc[4][4] = {};

    for (int k0 = 0; k0 < K; k0 += 16) {
#pragma unroll
        for (int i = 0; i < 4; i++) {
            int idx = t + i * 256;
            int r  = idx >> 4;     // 0..63
            int kk = idx & 15;
            int gr = row0 + r;
            As[kk][r] = (gr < M) ? A[(size_t)gr * K + k0 + kk] : 0.0f;
        }
#pragma unroll
        for (int i = 0; i < 4; i++) {
            int idx = t + i * 256;
            int kk = idx >> 6;     // 0..15
            int c  = idx & 63;
            Ws[kk][c] = W[(size_t)(k0 + kk) * Ncol + col0 + c];
        }
        __syncthreads();
#pragma unroll
        for (int kk = 0; kk < 16; kk++) {
            float4 am = *reinterpret_cast<const float4*>(&As[kk][ty * 4]);
            float4 wn = *reinterpret_cast<const float4*>(&Ws[kk][tx * 4]);
            float amv[4] = {am.x, am.y, am.z, am.w};
            float wnv[4] = {wn.x, wn.y, wn.z, wn.w};
#pragma unroll
            for (int i = 0; i < 4; i++)
#pragma unroll
                for (int j = 0; j < 4; j++)
                    acc[i][j] += amv[i] * wnv[j];
        }
        __syncthreads();
    }

#pragma unroll
    for (int i = 0; i < 4; i++) {
        int gr = row0 + ty * 4 + i;
        if (gr >= M) continue;
#pragma unroll
        for (int j = 0; j < 4; j++) {
            int gc = col0 + tx * 4 + j;
            C[(size_t)gr * Ncol + gc] = acc[i][j] + bias[gc];
        }
    }
}

// ---------------- layer-1 edge kernels (H=4, C=64) ----------------
// one warp per edge; lane handles 8 channels; 8-lane groups = heads
__global__ void edge_score1(const int* __restrict__ ei, int E, int N,
                            const float* __restrict__ att) {
    int warp = (blockIdx.x * blockDim.x + threadIdx.x) >> 5;
    int lane = threadIdx.x & 31;
    int ET = E + N;
    if (warp >= ET) return;
    int s, d;
    if (warp < E) { s = ei[warp]; d = ei[E + warp]; }
    else          { s = warp - E; d = s; }

    int c0 = lane * 8;
    const float4* xs = reinterpret_cast<const float4*>(g_xs1 + (size_t)s * 256 + c0);
    const float4* xd = reinterpret_cast<const float4*>(g_xd1 + (size_t)d * 256 + c0);
    const float4* at = reinterpret_cast<const float4*>(att + c0);

    float p = 0.0f;
#pragma unroll
    for (int i = 0; i < 2; i++) {
        float4 a = xs[i], b = xd[i], w = at[i];
        p += lrelu(a.x + b.x) * w.x;
        p += lrelu(a.y + b.y) * w.y;
        p += lrelu(a.z + b.z) * w.z;
        p += lrelu(a.w + b.w) * w.w;
    }
    p += __shfl_down_sync(0xffffffffu, p, 4, 8);
    p += __shfl_down_sync(0xffffffffu, p, 2, 8);
    p += __shfl_down_sync(0xffffffffu, p, 1, 8);
    if ((lane & 7) == 0) {
        int h = lane >> 3;
        g_score1[(size_t)warp * 4 + h] = p;
        atomicMax(&g_smax1[d * 4 + h], fenc(p));
    }
}

__global__ void edge_agg1(const int* __restrict__ ei, int E, int N) {
    int warp = (blockIdx.x * blockDim.x + threadIdx.x) >> 5;
    int lane = threadIdx.x & 31;
    int ET = E + N;
    if (warp >= ET) return;
    int s, d;
    if (warp < E) { s = ei[warp]; d = ei[E + warp]; }
    else          { s = warp - E; d = s; }

    int h = lane >> 3;
    float sc = g_score1[(size_t)warp * 4 + h];
    float mx = fdec(g_smax1[d * 4 + h]);
    float ex = __expf(sc - mx);
    if ((lane & 7) == 0) atomicAdd(&g_denom1[d * 4 + h], ex);

    int c0 = lane * 8;
    const float4* xs = reinterpret_cast<const float4*>(g_xs1 + (size_t)s * 256 + c0);
    float* dst = g_agg1 + (size_t)d * 256 + c0;
#pragma unroll
    for (int i = 0; i < 2; i++) {
        float4 a = xs[i];
        asm volatile("red.global.add.v4.f32 [%0], {%1,%2,%3,%4};"
                     :: "l"(dst + i * 4),
                        "f"(a.x * ex), "f"(a.y * ex), "f"(a.z * ex), "f"(a.w * ex)
                     : "memory");
    }
}

__global__ void node_fin1(const float* __restrict__ bias, int N) {
    size_t total = (size_t)N * 256;
    size_t stride = (size_t)gridDim.x * blockDim.x;
    for (size_t idx = (size_t)blockIdx.x * blockDim.x + threadIdx.x; idx < total; idx += stride) {
        int n = (int)(idx >> 8);
        int c = (int)(idx & 255);
        int h = c >> 6;
        float v = g_agg1[idx] / g_denom1[n * 4 + h] + bias[c];
        g_h[idx] = v > 0.0f ? v : 0.0f;   // relu
    }
}

// ---------------- layer-2 edge kernels (H=1, C=64) ----------------
__global__ void edge_score2(const int* __restrict__ ei, int E, int N,
                            const float* __restrict__ att) {
    int warp = (blockIdx.x * blockDim.x + threadIdx.x) >> 5;
    int lane = threadIdx.x & 31;
    int ET = E + N;
    if (warp >= ET) return;
    int s, d;
    if (warp < E) { s = ei[warp]; d = ei[E + warp]; }
    else          { s = warp - E; d = s; }

    int c0 = lane * 2;
    float2 a = *reinterpret_cast<const float2*>(g_xs2 + (size_t)s * 64 + c0);
    float2 b = *reinterpret_cast<const float2*>(g_xd2 + (size_t)d * 64 + c0);
    float2 w = *reinterpret_cast<const float2*>(att + c0);
    float p = lrelu(a.x + b.x) * w.x + lrelu(a.y + b.y) * w.y;
#pragma unroll
    for (int off = 16; off > 0; off >>= 1)
        p += __shfl_down_sync(0xffffffffu, p, off);
    if (lane == 0) {
        g_score2[warp] = p;
        atomicMax(&g_smax2[d], fenc(p));
    }
}

__global__ void edge_agg2(const int* __restrict__ ei, int E, int N) {
    int warp = (blockIdx.x * blockDim.x + threadIdx.x) >> 5;
    int lane = threadIdx.x & 31;
    int ET = E + N;
    if (warp >= ET) return;
    int s, d;
    if (warp < E) { s = ei[warp]; d = ei[E + warp]; }
    else          { s = warp - E; d = s; }

    float ex = __expf(g_score2[warp] - fdec(g_smax2[d]));
    if (lane == 0) atomicAdd(&g_denom2[d], ex);

    int c0 = lane * 2;
    float2 a = *reinterpret_cast<const float2*>(g_xs2 + (size_t)s * 64 + c0);
    float* dst = g_agg2 + (size_t)d * 64 + c0;
    asm volatile("red.global.add.v2.f32 [%0], {%1,%2};"
                 :: "l"(dst), "f"(a.x * ex), "f"(a.y * ex)
                 : "memory");
}

// finish layer 2 + pool accumulation
__global__ void node_fin2_pool(const float* __restrict__ bias,
                               const int* __restrict__ batch, int N) {
    size_t total = (size_t)N * 64;
    size_t stride = (size_t)gridDim.x * blockDim.x;
    for (size_t idx = (size_t)blockIdx.x * blockDim.x + threadIdx.x; idx < total; idx += stride) {
        int n = (int)(idx >> 6);
        int c = (int)(idx & 63);
        float v = g_agg2[idx] / g_denom2[n] + bias[c];
        int g = batch[n];
        atomicAdd(&g_pool[g * 64 + c], v);
        if (c == 0) atomicAdd(&g_cnt[g], 1.0f);
    }
}

__global__ void final_kernel(const float* __restrict__ Wlin,
                             const float* __restrict__ blin,
                             float* __restrict__ out) {
    int g = threadIdx.x;
    if (g >= NG) return;
    float cnt = g_cnt[g];
    if (cnt < 1.0f) cnt = 1.0f;
    float sum = 0.0f;
#pragma unroll
    for (int c = 0; c < 64; c++)
        sum += (g_pool[g * 64 + c] / cnt) * Wlin[c];
    out[g] = sum + blin[0];
}

// ---------------- launcher ----------------
extern "C" void kernel_launch(void* const* d_in, const int* in_sizes, int n_in,
                              void* d_out, int out_size) {
    const float* x      = (const float*)d_in[0];
    const int*   ei     = (const int*)d_in[1];
    const int*   batch  = (const int*)d_in[2];
    const float* W_l1   = (const float*)d_in[3];
    const float* b_l1   = (const float*)d_in[4];
    const float* W_r1   = (const float*)d_in[5];
    const float* b_r1   = (const float*)d_in[6];
    const float* att1   = (const float*)d_in[7];
    const float* bias1  = (const float*)d_in[8];
    const float* W_l2   = (const float*)d_in[9];
    const float* b_l2   = (const float*)d_in[10];
    const float* W_r2   = (const float*)d_in[11];
    const float* b_r2   = (const float*)d_in[12];
    const float* att2   = (const float*)d_in[13];
    const float* bias2  = (const float*)d_in[14];
    const float* W_lin  = (const float*)d_in[15];
    const float* b_lin  = (const float*)d_in[16];
    float* out = (float*)d_out;

    const int N = in_sizes[0] / 128;   // 50000
    const int E = in_sizes[1] / 2;     // 800000
    const int ET = E + N;

    // CRITICAL: __device__ symbol names in host code are host-shadow
    // addresses. Resolve the real device addresses for pointers we pass
    // as kernel arguments. (Host-side query; no alloc; capture-safe.)
    float *p_xs1, *p_xd1, *p_h, *p_xs2, *p_xd2;
    cudaGetSymbolAddress((void**)&p_xs1, g_xs1);
    cudaGetSymbolAddress((void**)&p_xd1, g_xd1);
    cudaGetSymbolAddress((void**)&p_h,   g_h);
    cudaGetSymbolAddress((void**)&p_xs2, g_xs2);
    cudaGetSymbolAddress((void**)&p_xd2, g_xd2);

    // init scratch
    init_kernel<<<2048, 256>>>(N);

    // layer 1 transforms
    {
        dim3 grid(256 / 64, (N + 63) / 64);
        gemm_bias<<<grid, 256>>>(x, W_l1, b_l1, p_xs1, N, 128, 256);
        gemm_bias<<<grid, 256>>>(x, W_r1, b_r1, p_xd1, N, 128, 256);
    }

    // layer 1 edges
    {
        int blocks = (int)(((long long)ET * 32 + 255) / 256);
        edge_score1<<<blocks, 256>>>(ei, E, N, att1);
        edge_agg1<<<blocks, 256>>>(ei, E, N);
    }
    node_fin1<<<4096, 256>>>(bias1, N);

    // layer 2 transforms
    {
        dim3 grid(1, (N + 63) / 64);
        gemm_bias<<<grid, 256>>>(p_h, W_l2, b_l2, p_xs2, N, 256, 64);
        gemm_bias<<<grid, 256>>>(p_h, W_r2, b_r2, p_xd2, N, 256, 64);
    }

    // layer 2 edges
    {
        int blocks = (int)(((long long)ET * 32 + 255) / 256);
        edge_score2<<<blocks, 256>>>(ei, E, N, att2);
        edge_agg2<<<blocks, 256>>>(ei, E, N);
    }

    // finish layer 2 + pooling
    node_fin2_pool<<<2048, 256>>>(bias2, batch, N);

    final_kernel<<<1, 64>>>(W_lin, b_lin, out);
}

// round 3
// speedup vs baseline: 1.8769x; 1.8769x over previous
#include <cuda_runtime.h>
#include <cstdint>
#include <math_constants.h>

// ---------------- problem-size constants ----------------
#define MAXN 50000
#define MAXE 800000
#define MAXET (MAXE + MAXN)   // edges + self loops
#define NG 64                 // graphs

// ---------------- scratch (device globals; allocation-free) ----------------
__device__ float g_xs1[(size_t)MAXN * 256];
__device__ float g_xd1[(size_t)MAXN * 256];
__device__ float g_h  [(size_t)MAXN * 256];
__device__ float g_xs2[(size_t)MAXN * 64];
__device__ float g_xd2[(size_t)MAXN * 64];

__device__ int   g_deg[MAXN];
__device__ int   g_rowptr[MAXN + 1];
__device__ int   g_cursor[MAXN];
__device__ int   g_csr_src[MAXET];

__device__ float g_pool[NG * 64];
__device__ float g_cnt[NG];

__device__ __forceinline__ float lrelu(float v) {
    return v > 0.0f ? v : 0.2f * v;
}

// ---------------- zero / init ----------------
__global__ void zero_kernel(int N) {
    int i = blockIdx.x * blockDim.x + threadIdx.x;
    int stride = gridDim.x * blockDim.x;
    for (int k = i; k < N; k += stride) g_deg[k] = 0;
    if (i < NG * 64) g_pool[i] = 0.0f;
    if (i < NG)      g_cnt[i] = 0.0f;
}

// ---------------- CSR build ----------------
__global__ void hist_kernel(const int* __restrict__ ei, int E, int N) {
    int i = blockIdx.x * blockDim.x + threadIdx.x;
    int ET = E + N;
    if (i >= ET) return;
    int d = (i < E) ? ei[E + i] : (i - E);
    atomicAdd(&g_deg[d], 1);
}

// single block, 1024 threads: exclusive scan of g_deg into g_rowptr (+cursor copy)
__global__ void scan_kernel(int N) {
    __shared__ int ssum[1024];
    int t = threadIdx.x;
    int chunk = (N + 1023) >> 10;
    int b = t * chunk;
    int e = b + chunk; if (e > N) e = N;
    int s = 0;
    for (int i = b; i < e; i++) s += g_deg[i];
    ssum[t] = s;
    __syncthreads();
    // Hillis-Steele inclusive scan
    for (int off = 1; off < 1024; off <<= 1) {
        int v = (t >= off) ? ssum[t - off] : 0;
        __syncthreads();
        ssum[t] += v;
        __syncthreads();
    }
    int run = (t == 0) ? 0 : ssum[t - 1];
    for (int i = b; i < e; i++) {
        g_rowptr[i] = run;
        g_cursor[i] = run;
        run += g_deg[i];
    }
    if (t == 1023) g_rowptr[N] = ssum[1023];
}

__global__ void scatter_kernel(const int* __restrict__ ei, int E, int N) {
    int i = blockIdx.x * blockDim.x + threadIdx.x;
    int ET = E + N;
    if (i >= ET) return;
    int s, d;
    if (i < E) { s = ei[i]; d = ei[E + i]; }
    else       { s = i - E; d = s; }
    int pos = atomicAdd(&g_cursor[d], 1);
    g_csr_src[pos] = s;
}

// ---------------- GEMM: C[M,Ncol] = A[M,K] @ W[K,Ncol] + bias ----------------
// BM=128, BN=64, BK=16, 256 threads, 8x4 per thread
__global__ void gemm_bias(const float* __restrict__ A, const float* __restrict__ W,
                          const float* __restrict__ bias, float* __restrict__ C,
                          int M, int K, int Ncol) {
    // As stored as float4 slabs: As4[kk4][r] holds k = kk4*4..kk4*4+3 for row r
    __shared__ float4 As4[4][128];
    __shared__ float  Ws[16][64];
    const int t  = threadIdx.x;
    const int tx = t & 15;     // 16 col groups of 4
    const int ty = t >> 4;     // 16 row groups of 8
    const int row0 = blockIdx.y * 128;
    const int col0 = blockIdx.x * 64;

    float acc[8][4] = {};

    for (int k0 = 0; k0 < K; k0 += 16) {
        // load A tile: 512 float4 slots over 256 threads
#pragma unroll
        for (int i = 0; i < 2; i++) {
            int linear = t + i * 256;
            int r   = linear >> 2;
            int kk4 = linear & 3;
            int gr = row0 + r;
            float4 v = make_float4(0.f, 0.f, 0.f, 0.f);
            if (gr < M)
                v = *reinterpret_cast<const float4*>(&A[(size_t)gr * K + k0 + kk4 * 4]);
            As4[kk4][r] = v;
        }
        // load W tile: 256 float4 slots
        {
            int kk = t >> 4;
            int c4 = t & 15;
            float4 v = *reinterpret_cast<const float4*>(&W[(size_t)(k0 + kk) * Ncol + col0 + c4 * 4]);
            *reinterpret_cast<float4*>(&Ws[kk][c4 * 4]) = v;
        }
        __syncthreads();

#pragma unroll
        for (int kk4 = 0; kk4 < 4; kk4++) {
            float4 af[8];
#pragma unroll
            for (int i = 0; i < 8; i++) af[i] = As4[kk4][ty * 8 + i];
            const float* ap = reinterpret_cast<const float*>(af);
#pragma unroll
            for (int j4 = 0; j4 < 4; j4++) {
                float4 b = *reinterpret_cast<const float4*>(&Ws[(kk4 << 2) + j4][tx << 2]);
#pragma unroll
                for (int i = 0; i < 8; i++) {
                    float av = ap[i * 4 + j4];
                    acc[i][0] += av * b.x;
                    acc[i][1] += av * b.y;
                    acc[i][2] += av * b.z;
                    acc[i][3] += av * b.w;
                }
            }
        }
        __syncthreads();
    }

    int gc = col0 + tx * 4;
    float4 bv = *reinterpret_cast<const float4*>(&bias[gc]);
#pragma unroll
    for (int i = 0; i < 8; i++) {
        int gr = row0 + ty * 8 + i;
        if (gr >= M) continue;
        float4 o;
        o.x = acc[i][0] + bv.x;
        o.y = acc[i][1] + bv.y;
        o.z = acc[i][2] + bv.z;
        o.w = acc[i][3] + bv.w;
        *reinterpret_cast<float4*>(&C[(size_t)gr * Ncol + gc]) = o;
    }
}

// ---------------- fused layer-1 node pass (H=4, C=64) ----------------
// one warp per dst node; online softmax + aggregation; epilogue bias+relu -> g_h
__global__ void fused_gat1(const float* __restrict__ att,
                           const float* __restrict__ bias, int N) {
    int warp = (blockIdx.x * blockDim.x + threadIdx.x) >> 5;
    if (warp >= N) return;
    int lane = threadIdx.x & 31;
    int n = warp;
    int c0 = lane * 8;   // 8 channels per lane; lanes 0-7 = head0, etc.

    const float4* xdp = reinterpret_cast<const float4*>(g_xd1 + (size_t)n * 256 + c0);
    float4 d0 = xdp[0], d1 = xdp[1];
    float4 w0 = *reinterpret_cast<const float4*>(att + c0);
    float4 w1 = *reinterpret_cast<const float4*>(att + c0 + 4);

    float m = -CUDART_INF_F, s = 0.0f;
    float acc[8] = {0, 0, 0, 0, 0, 0, 0, 0};

    int beg = g_rowptr[n], end = g_rowptr[n + 1];
    for (int e = beg; e < end; e++) {
        int src = g_csr_src[e];
        const float4* xsp = reinterpret_cast<const float4*>(g_xs1 + (size_t)src * 256 + c0);
        float4 a0 = xsp[0], a1 = xsp[1];

        float p = lrelu(a0.x + d0.x) * w0.x + lrelu(a0.y + d0.y) * w0.y
                + lrelu(a0.z + d0.z) * w0.z + lrelu(a0.w + d0.w) * w0.w
                + lrelu(a1.x + d1.x) * w1.x + lrelu(a1.y + d1.y) * w1.y
                + lrelu(a1.z + d1.z) * w1.z + lrelu(a1.w + d1.w) * w1.w;
        // all-lane sum within 8-lane head group
        p += __shfl_xor_sync(0xffffffffu, p, 4);
        p += __shfl_xor_sync(0xffffffffu, p, 2);
        p += __shfl_xor_sync(0xffffffffu, p, 1);

        float m_new = fmaxf(m, p);
        float scale = __expf(m - m_new);   // 0 on first edge (m = -inf)
        float ex    = __expf(p - m_new);
        s = s * scale + ex;
        acc[0] = acc[0] * scale + ex * a0.x;
        acc[1] = acc[1] * scale + ex * a0.y;
        acc[2] = acc[2] * scale + ex * a0.z;
        acc[3] = acc[3] * scale + ex * a0.w;
        acc[4] = acc[4] * scale + ex * a1.x;
        acc[5] = acc[5] * scale + ex * a1.y;
        acc[6] = acc[6] * scale + ex * a1.z;
        acc[7] = acc[7] * scale + ex * a1.w;
        m = m_new;
    }

    float inv = 1.0f / s;
    float4 b0 = *reinterpret_cast<const float4*>(bias + c0);
    float4 b1 = *reinterpret_cast<const float4*>(bias + c0 + 4);
    float4 o0, o1;
    o0.x = fmaxf(acc[0] * inv + b0.x, 0.0f);
    o0.y = fmaxf(acc[1] * inv + b0.y, 0.0f);
    o0.z = fmaxf(acc[2] * inv + b0.z, 0.0f);
    o0.w = fmaxf(acc[3] * inv + b0.w, 0.0f);
    o1.x = fmaxf(acc[4] * inv + b1.x, 0.0f);
    o1.y = fmaxf(acc[5] * inv + b1.y, 0.0f);
    o1.z = fmaxf(acc[6] * inv + b1.z, 0.0f);
    o1.w = fmaxf(acc[7] * inv + b1.w, 0.0f);
    float4* hp = reinterpret_cast<float4*>(g_h + (size_t)n * 256 + c0);
    hp[0] = o0;
    hp[1] = o1;
}

// ---------------- fused layer-2 node pass (H=1, C=64) + pool ----------------
__global__ void fused_gat2(const float* __restrict__ att,
                           const float* __restrict__ bias,
                           const int* __restrict__ batch, int N) {
    int warp = (blockIdx.x * blockDim.x + threadIdx.x) >> 5;
    if (warp >= N) return;
    int lane = threadIdx.x & 31;
    int n = warp;
    int c0 = lane * 2;

    float2 d = *reinterpret_cast<const float2*>(g_xd2 + (size_t)n * 64 + c0);
    float2 w = *reinterpret_cast<const float2*>(att + c0);

    float m = -CUDART_INF_F, s = 0.0f;
    float acc0 = 0.0f, acc1 = 0.0f;

    int beg = g_rowptr[n], end = g_rowptr[n + 1];
    for (int e = beg; e < end; e++) {
        int src = g_csr_src[e];
        float2 a = *reinterpret_cast<const float2*>(g_xs2 + (size_t)src * 64 + c0);
        float p = lrelu(a.x + d.x) * w.x + lrelu(a.y + d.y) * w.y;
        p += __shfl_xor_sync(0xffffffffu, p, 16);
        p += __shfl_xor_sync(0xffffffffu, p, 8);
        p += __shfl_xor_sync(0xffffffffu, p, 4);
        p += __shfl_xor_sync(0xffffffffu, p, 2);
        p += __shfl_xor_sync(0xffffffffu, p, 1);

        float m_new = fmaxf(m, p);
        float scale = __expf(m - m_new);
        float ex    = __expf(p - m_new);
        s = s * scale + ex;
        acc0 = acc0 * scale + ex * a.x;
        acc1 = acc1 * scale + ex * a.y;
        m = m_new;
    }

    float inv = 1.0f / s;
    float v0 = acc0 * inv + bias[c0];
    float v1 = acc1 * inv + bias[c0 + 1];

    int g = batch[n];
    atomicAdd(&g_pool[g * 64 + c0], v0);
    atomicAdd(&g_pool[g * 64 + c0 + 1], v1);
    if (lane == 0) atomicAdd(&g_cnt[g], 1.0f);
}

__global__ void final_kernel(const float* __restrict__ Wlin,
                             const float* __restrict__ blin,
                             float* __restrict__ out) {
    int g = threadIdx.x;
    if (g >= NG) return;
    float cnt = g_cnt[g];
    if (cnt < 1.0f) cnt = 1.0f;
    float sum = 0.0f;
#pragma unroll
    for (int c = 0; c < 64; c++)
        sum += (g_pool[g * 64 + c] / cnt) * Wlin[c];
    out[g] = sum + blin[0];
}

// ---------------- launcher ----------------
extern "C" void kernel_launch(void* const* d_in, const int* in_sizes, int n_in,
                              void* d_out, int out_size) {
    const float* x      = (const float*)d_in[0];
    const int*   ei     = (const int*)d_in[1];
    const int*   batch  = (const int*)d_in[2];
    const float* W_l1   = (const float*)d_in[3];
    const float* b_l1   = (const float*)d_in[4];
    const float* W_r1   = (const float*)d_in[5];
    const float* b_r1   = (const float*)d_in[6];
    const float* att1   = (const float*)d_in[7];
    const float* bias1  = (const float*)d_in[8];
    const float* W_l2   = (const float*)d_in[9];
    const float* b_l2   = (const float*)d_in[10];
    const float* W_r2   = (const float*)d_in[11];
    const float* b_r2   = (const float*)d_in[12];
    const float* att2   = (const float*)d_in[13];
    const float* bias2  = (const float*)d_in[14];
    const float* W_lin  = (const float*)d_in[15];
    const float* b_lin  = (const float*)d_in[16];
    float* out = (float*)d_out;

    const int N = in_sizes[0] / 128;   // 50000
    const int E = in_sizes[1] / 2;     // 800000
    const int ET = E + N;

    // __device__ symbols -> real device pointers (host-side query; capture-safe)
    float *p_xs1, *p_xd1, *p_h, *p_xs2, *p_xd2;
    cudaGetSymbolAddress((void**)&p_xs1, g_xs1);
    cudaGetSymbolAddress((void**)&p_xd1, g_xd1);
    cudaGetSymbolAddress((void**)&p_h,   g_h);
    cudaGetSymbolAddress((void**)&p_xs2, g_xs2);
    cudaGetSymbolAddress((void**)&p_xd2, g_xd2);

    // init + CSR build
    zero_kernel<<<256, 256>>>(N);
    hist_kernel<<<(ET + 255) / 256, 256>>>(ei, E, N);
    scan_kernel<<<1, 1024>>>(N);
    scatter_kernel<<<(ET + 255) / 256, 256>>>(ei, E, N);

    // layer 1 transforms
    {
        dim3 grid(256 / 64, (N + 127) / 128);
        gemm_bias<<<grid, 256>>>(x, W_l1, b_l1, p_xs1, N, 128, 256);
        gemm_bias<<<grid, 256>>>(x, W_r1, b_r1, p_xd1, N, 128, 256);
    }

    // fused layer-1 attention + aggregation (+ bias + relu)
    fused_gat1<<<(N * 32 + 255) / 256, 256>>>(att1, bias1, N);

    // layer 2 transforms
    {
        dim3 grid(1, (N + 127) / 128);
        gemm_bias<<<grid, 256>>>(p_h, W_l2, b_l2, p_xs2, N, 256, 64);
        gemm_bias<<<grid, 256>>>(p_h, W_r2, b_r2, p_xd2, N, 256, 64);
    }

    // fused layer-2 attention + aggregation + pooling
    fused_gat2<<<(N * 32 + 255) / 256, 256>>>(att2, bias2, batch, N);

    final_kernel<<<1, 64>>>(W_lin, b_lin, out);
}

// round 4
// speedup vs baseline: 2.6426x; 1.4080x over previous
#include <cuda_runtime.h>
#include <cstdint>
#include <math_constants.h>

// ---------------- problem-size constants ----------------
#define MAXN 50000
#define MAXE 800000
#define MAXET (MAXE + MAXN)   // edges + self loops
#define NG 64                 // graphs

// ---------------- scratch (device globals; allocation-free) ----------------
__device__ float g_xs1[(size_t)MAXN * 256];
__device__ float g_xd1[(size_t)MAXN * 256];
__device__ float g_h  [(size_t)MAXN * 256];
__device__ float g_xs2[(size_t)MAXN * 64];
__device__ float g_xd2[(size_t)MAXN * 64];

__device__ int   g_deg[MAXN];
__device__ int   g_rowptr[MAXN + 1];
__device__ int   g_cursor[MAXN];
__device__ int   g_csr_src[MAXET];

__device__ float g_pool[NG * 64];
__device__ float g_cnt[NG];

__device__ __forceinline__ float lrelu(float v) {
    return v > 0.0f ? v : 0.2f * v;
}

__device__ __forceinline__ unsigned f2tf32(float f) {
    unsigned r;
    asm("cvt.rna.tf32.f32 %0, %1;" : "=r"(r) : "f"(f));
    return r;
}

__device__ __forceinline__ void mma_tf32(float* c, const unsigned* a, const unsigned* b) {
    asm volatile(
        "mma.sync.aligned.m16n8k8.row.col.f32.tf32.tf32.f32 "
        "{%0,%1,%2,%3}, {%4,%5,%6,%7}, {%8,%9}, {%0,%1,%2,%3};"
        : "+f"(c[0]), "+f"(c[1]), "+f"(c[2]), "+f"(c[3])
        : "r"(a[0]), "r"(a[1]), "r"(a[2]), "r"(a[3]), "r"(b[0]), "r"(b[1]));
}

// ---------------- zero / init ----------------
__global__ void zero_kernel(int N) {
    int i = blockIdx.x * blockDim.x + threadIdx.x;
    int stride = gridDim.x * blockDim.x;
    for (int k = i; k < N; k += stride) g_deg[k] = 0;
    if (i < NG * 64) g_pool[i] = 0.0f;
    if (i < NG)      g_cnt[i] = 0.0f;
}

// ---------------- CSR build ----------------
__global__ void hist_kernel(const int* __restrict__ ei, int E, int N) {
    int i = blockIdx.x * blockDim.x + threadIdx.x;
    int ET = E + N;
    if (i >= ET) return;
    int d = (i < E) ? ei[E + i] : (i - E);
    atomicAdd(&g_deg[d], 1);
}

// single block, 1024 threads: exclusive scan of g_deg into g_rowptr (+cursor copy)
__global__ void scan_kernel(int N) {
    __shared__ int ssum[1024];
    int t = threadIdx.x;
    int chunk = (N + 1023) >> 10;
    int b = t * chunk;
    int e = b + chunk; if (e > N) e = N;
    int s = 0;
    for (int i = b; i < e; i++) s += g_deg[i];
    ssum[t] = s;
    __syncthreads();
    for (int off = 1; off < 1024; off <<= 1) {
        int v = (t >= off) ? ssum[t - off] : 0;
        __syncthreads();
        ssum[t] += v;
        __syncthreads();
    }
    int run = (t == 0) ? 0 : ssum[t - 1];
    for (int i = b; i < e; i++) {
        g_rowptr[i] = run;
        g_cursor[i] = run;
        run += g_deg[i];
    }
    if (t == 1023) g_rowptr[N] = ssum[1023];
}

__global__ void scatter_kernel(const int* __restrict__ ei, int E, int N) {
    int i = blockIdx.x * blockDim.x + threadIdx.x;
    int ET = E + N;
    if (i >= ET) return;
    int s, d;
    if (i < E) { s = ei[i]; d = ei[E + i]; }
    else       { s = i - E; d = s; }
    int pos = atomicAdd(&g_cursor[d], 1);
    g_csr_src[pos] = s;
}

// ---------------- tf32 tensor-core GEMM ----------------
// C[M,Ncol] = A[M,K] @ W[K,Ncol] + bias
// Tile: BM=128, BN=64, BK=32; 256 threads = 8 warps (4m x 2n).
// blockIdx.z selects (W0,b0,C0) vs (W1,b1,C1) — both transforms in one launch.
__global__ void gemm_tf32_dual(const float* __restrict__ A,
                               const float* __restrict__ W0, const float* __restrict__ b0,
                               float* __restrict__ C0,
                               const float* __restrict__ W1, const float* __restrict__ b1,
                               float* __restrict__ C1,
                               int M, int K, int Ncol) {
    const float* W    = blockIdx.z ? W1 : W0;
    const float* bias = blockIdx.z ? b1 : b0;
    float*       C    = blockIdx.z ? C1 : C0;

    __shared__ float As[128][36];   // stride 36: conflict-free frag loads
    __shared__ float Bs[32][68];

    const int t    = threadIdx.x;
    const int lane = t & 31;
    const int warp = t >> 5;
    const int grp  = lane >> 2;   // 0..7
    const int tg   = lane & 3;    // 0..3
    const int warp_m = warp & 3;  // 4 warps along M (32 rows each)
    const int warp_n = warp >> 2; // 2 warps along N (32 cols each)

    const int row0 = blockIdx.y * 128;
    const int col0 = blockIdx.x * 64;

    float acc[2][4][4];
#pragma unroll
    for (int mi = 0; mi < 2; mi++)
#pragma unroll
        for (int ni = 0; ni < 4; ni++)
#pragma unroll
            for (int j = 0; j < 4; j++) acc[mi][ni][j] = 0.0f;

    for (int k0 = 0; k0 < K; k0 += 32) {
        // A tile: 128 rows x 32 cols = 1024 float4 over 256 threads
#pragma unroll
        for (int i = 0; i < 4; i++) {
            int idx = t + i * 256;
            int r  = idx >> 3;
            int c4 = idx & 7;
            int gr = row0 + r;
            float4 v = make_float4(0.f, 0.f, 0.f, 0.f);
            if (gr < M)
                v = *reinterpret_cast<const float4*>(&A[(size_t)gr * K + k0 + c4 * 4]);
            *reinterpret_cast<float4*>(&As[r][c4 * 4]) = v;
        }
        // B tile: 32 rows x 64 cols = 512 float4
#pragma unroll
        for (int i = 0; i < 2; i++) {
            int idx = t + i * 256;
            int kk = idx >> 4;
            int c4 = idx & 15;
            float4 v = *reinterpret_cast<const float4*>(&W[(size_t)(k0 + kk) * Ncol + col0 + c4 * 4]);
            *reinterpret_cast<float4*>(&Bs[kk][c4 * 4]) = v;
        }
        __syncthreads();

#pragma unroll
        for (int ks = 0; ks < 32; ks += 8) {
            unsigned af[2][4];
#pragma unroll
            for (int mi = 0; mi < 2; mi++) {
                int r = warp_m * 32 + mi * 16 + grp;
                af[mi][0] = f2tf32(As[r][ks + tg]);
                af[mi][1] = f2tf32(As[r + 8][ks + tg]);
                af[mi][2] = f2tf32(As[r][ks + tg + 4]);
                af[mi][3] = f2tf32(As[r + 8][ks + tg + 4]);
            }
            unsigned bf[4][2];
#pragma unroll
            for (int ni = 0; ni < 4; ni++) {
                int c = warp_n * 32 + ni * 8 + grp;
                bf[ni][0] = f2tf32(Bs[ks + tg][c]);
                bf[ni][1] = f2tf32(Bs[ks + tg + 4][c]);
            }
#pragma unroll
            for (int mi = 0; mi < 2; mi++)
#pragma unroll
                for (int ni = 0; ni < 4; ni++)
                    mma_tf32(acc[mi][ni], af[mi], bf[ni]);
        }
        __syncthreads();
    }

    // epilogue: c0,c1 -> (row, 2tg), (row, 2tg+1); c2,c3 -> row+8
#pragma unroll
    for (int ni = 0; ni < 4; ni++) {
        int gc = col0 + warp_n * 32 + ni * 8 + tg * 2;
        float2 bv = *reinterpret_cast<const float2*>(&bias[gc]);
#pragma unroll
        for (int mi = 0; mi < 2; mi++) {
            int gr = row0 + warp_m * 32 + mi * 16 + grp;
            if (gr < M) {
                float2 o = make_float2(acc[mi][ni][0] + bv.x, acc[mi][ni][1] + bv.y);
                *reinterpret_cast<float2*>(&C[(size_t)gr * Ncol + gc]) = o;
            }
            if (gr + 8 < M) {
                float2 o = make_float2(acc[mi][ni][2] + bv.x, acc[mi][ni][3] + bv.y);
                *reinterpret_cast<float2*>(&C[(size_t)(gr + 8) * Ncol + gc]) = o;
            }
        }
    }
}

// ---------------- fused layer-1 node pass (H=4, C=64) ----------------
__global__ void fused_gat1(const float* __restrict__ att,
                           const float* __restrict__ bias, int N) {
    int warp = (blockIdx.x * blockDim.x + threadIdx.x) >> 5;
    if (warp >= N) return;
    int lane = threadIdx.x & 31;
    int n = warp;
    int c0 = lane * 8;   // 8 channels per lane; lanes 0-7 = head0, etc.

    const float4* xdp = reinterpret_cast<const float4*>(g_xd1 + (size_t)n * 256 + c0);
    float4 d0 = xdp[0], d1 = xdp[1];
    float4 w0 = *reinterpret_cast<const float4*>(att + c0);
    float4 w1 = *reinterpret_cast<const float4*>(att + c0 + 4);

    float m = -CUDART_INF_F, s = 0.0f;
    float acc[8] = {0, 0, 0, 0, 0, 0, 0, 0};

    int beg = g_rowptr[n], end = g_rowptr[n + 1];
    for (int e = beg; e < end; e++) {
        int src = g_csr_src[e];
        const float4* xsp = reinterpret_cast<const float4*>(g_xs1 + (size_t)src * 256 + c0);
        float4 a0 = xsp[0], a1 = xsp[1];

        float p = lrelu(a0.x + d0.x) * w0.x + lrelu(a0.y + d0.y) * w0.y
                + lrelu(a0.z + d0.z) * w0.z + lrelu(a0.w + d0.w) * w0.w
                + lrelu(a1.x + d1.x) * w1.x + lrelu(a1.y + d1.y) * w1.y
                + lrelu(a1.z + d1.z) * w1.z + lrelu(a1.w + d1.w) * w1.w;
        p += __shfl_xor_sync(0xffffffffu, p, 4);
        p += __shfl_xor_sync(0xffffffffu, p, 2);
        p += __shfl_xor_sync(0xffffffffu, p, 1);

        float m_new = fmaxf(m, p);
        float scale = __expf(m - m_new);
        float ex    = __expf(p - m_new);
        s = s * scale + ex;
        acc[0] = acc[0] * scale + ex * a0.x;
        acc[1] = acc[1] * scale + ex * a0.y;
        acc[2] = acc[2] * scale + ex * a0.z;
        acc[3] = acc[3] * scale + ex * a0.w;
        acc[4] = acc[4] * scale + ex * a1.x;
        acc[5] = acc[5] * scale + ex * a1.y;
        acc[6] = acc[6] * scale + ex * a1.z;
        acc[7] = acc[7] * scale + ex * a1.w;
        m = m_new;
    }

    float inv = 1.0f / s;
    float4 b0 = *reinterpret_cast<const float4*>(bias + c0);
    float4 b1 = *reinterpret_cast<const float4*>(bias + c0 + 4);
    float4 o0, o1;
    o0.x = fmaxf(acc[0] * inv + b0.x, 0.0f);
    o0.y = fmaxf(acc[1] * inv + b0.y, 0.0f);
    o0.z = fmaxf(acc[2] * inv + b0.z, 0.0f);
    o0.w = fmaxf(acc[3] * inv + b0.w, 0.0f);
    o1.x = fmaxf(acc[4] * inv + b1.x, 0.0f);
    o1.y = fmaxf(acc[5] * inv + b1.y, 0.0f);
    o1.z = fmaxf(acc[6] * inv + b1.z, 0.0f);
    o1.w = fmaxf(acc[7] * inv + b1.w, 0.0f);
    float4* hp = reinterpret_cast<float4*>(g_h + (size_t)n * 256 + c0);
    hp[0] = o0;
    hp[1] = o1;
}

// ---------------- fused layer-2 node pass (H=1, C=64) + pool ----------------
__global__ void fused_gat2(const float* __restrict__ att,
                           const float* __restrict__ bias,
                           const int* __restrict__ batch, int N) {
    int warp = (blockIdx.x * blockDim.x + threadIdx.x) >> 5;
    if (warp >= N) return;
    int lane = threadIdx.x & 31;
    int n = warp;
    int c0 = lane * 2;

    float2 d = *reinterpret_cast<const float2*>(g_xd2 + (size_t)n * 64 + c0);
    float2 w = *reinterpret_cast<const float2*>(att + c0);

    float m = -CUDART_INF_F, s = 0.0f;
    float acc0 = 0.0f, acc1 = 0.0f;

    int beg = g_rowptr[n], end = g_rowptr[n + 1];
    for (int e = beg; e < end; e++) {
        int src = g_csr_src[e];
        float2 a = *reinterpret_cast<const float2*>(g_xs2 + (size_t)src * 64 + c0);
        float p = lrelu(a.x + d.x) * w.x + lrelu(a.y + d.y) * w.y;
        p += __shfl_xor_sync(0xffffffffu, p, 16);
        p += __shfl_xor_sync(0xffffffffu, p, 8);
        p += __shfl_xor_sync(0xffffffffu, p, 4);
        p += __shfl_xor_sync(0xffffffffu, p, 2);
        p += __shfl_xor_sync(0xffffffffu, p, 1);

        float m_new = fmaxf(m, p);
        float scale = __expf(m - m_new);
        float ex    = __expf(p - m_new);
        s = s * scale + ex;
        acc0 = acc0 * scale + ex * a.x;
        acc1 = acc1 * scale + ex * a.y;
        m = m_new;
    }

    float inv = 1.0f / s;
    float v0 = acc0 * inv + bias[c0];
    float v1 = acc1 * inv + bias[c0 + 1];

    int g = batch[n];
    atomicAdd(&g_pool[g * 64 + c0], v0);
    atomicAdd(&g_pool[g * 64 + c0 + 1], v1);
    if (lane == 0) atomicAdd(&g_cnt[g], 1.0f);
}

__global__ void final_kernel(const float* __restrict__ Wlin,
                             const float* __restrict__ blin,
                             float* __restrict__ out) {
    int g = threadIdx.x;
    if (g >= NG) return;
    float cnt = g_cnt[g];
    if (cnt < 1.0f) cnt = 1.0f;
    float sum = 0.0f;
#pragma unroll
    for (int c = 0; c < 64; c++)
        sum += (g_pool[g * 64 + c] / cnt) * Wlin[c];
    out[g] = sum + blin[0];
}

// ---------------- launcher ----------------
extern "C" void kernel_launch(void* const* d_in, const int* in_sizes, int n_in,
                              void* d_out, int out_size) {
    const float* x      = (const float*)d_in[0];
    const int*   ei     = (const int*)d_in[1];
    const int*   batch  = (const int*)d_in[2];
    const float* W_l1   = (const float*)d_in[3];
    const float* b_l1   = (const float*)d_in[4];
    const float* W_r1   = (const float*)d_in[5];
    const float* b_r1   = (const float*)d_in[6];
    const float* att1   = (const float*)d_in[7];
    const float* bias1  = (const float*)d_in[8];
    const float* W_l2   = (const float*)d_in[9];
    const float* b_l2   = (const float*)d_in[10];
    const float* W_r2   = (const float*)d_in[11];
    const float* b_r2   = (const float*)d_in[12];
    const float* att2   = (const float*)d_in[13];
    const float* bias2  = (const float*)d_in[14];
    const float* W_lin  = (const float*)d_in[15];
    const float* b_lin  = (const float*)d_in[16];
    float* out = (float*)d_out;

    const int N = in_sizes[0] / 128;   // 50000
    const int E = in_sizes[1] / 2;     // 800000
    const int ET = E + N;

    // __device__ symbols -> real device pointers (host-side query; capture-safe)
    float *p_xs1, *p_xd1, *p_h, *p_xs2, *p_xd2;
    cudaGetSymbolAddress((void**)&p_xs1, g_xs1);
    cudaGetSymbolAddress((void**)&p_xd1, g_xd1);
    cudaGetSymbolAddress((void**)&p_h,   g_h);
    cudaGetSymbolAddress((void**)&p_xs2, g_xs2);
    cudaGetSymbolAddress((void**)&p_xd2, g_xd2);

    // init + CSR build
    zero_kernel<<<256, 256>>>(N);
    hist_kernel<<<(ET + 255) / 256, 256>>>(ei, E, N);
    scan_kernel<<<1, 1024>>>(N);
    scatter_kernel<<<(ET + 255) / 256, 256>>>(ei, E, N);

    const int mblocks = (N + 127) / 128;

    // layer 1 transforms: xs1 = x@Wl1+b, xd1 = x@Wr1+b (z dim picks which)
    {
        dim3 grid(256 / 64, mblocks, 2);
        gemm_tf32_dual<<<grid, 256>>>(x, W_l1, b_l1, p_xs1, W_r1, b_r1, p_xd1,
                                      N, 128, 256);
    }

    // fused layer-1 attention + aggregation (+ bias + relu)
    fused_gat1<<<(N * 32 + 255) / 256, 256>>>(att1, bias1, N);

    // layer 2 transforms
    {
        dim3 grid(1, mblocks, 2);
        gemm_tf32_dual<<<grid, 256>>>(p_h, W_l2, b_l2, p_xs2, W_r2, b_r2, p_xd2,
                                      N, 256, 64);
    }

    // fused layer-2 attention + aggregation + pooling
    fused_gat2<<<(N * 32 + 255) / 256, 256>>>(att2, bias2, batch, N);

    final_kernel<<<1, 64>>>(W_lin, b_lin, out);
}